// round 11
// baseline (speedup 1.0000x reference)
#include <cuda_runtime.h>
#include <cuda_bf16.h>

// RoIAlign1D: feat [B,T,D] f32, spans [B,K,2] i32, lengths [B] i32 -> out [B,K,P,D] f32
// P = 16, D = 512 (128 float4).
//
// R11: persistent grid at the exact occupancy cap: 148*16 = 2368 blocks of 128
// threads, each grid-striding over 8192 (RoI, 2-sample) items (3-4 items per
// block, zero CTA churn). Per item identical to R6 (best: 10.7us): 4-burst
// LDG.128, FFMA lerp, __stcs stores, default L1-cached feat loads. The next
// item's spans/lengths are prefetched BEFORE consuming the current feat loads,
// hiding the scalar-load head latency of every item after the first.

#define P_SAMPLES 16
#define PG 2   // samples per work item

__global__ void __launch_bounds__(128, 16) roialign1d_kernel(
    const float4* __restrict__ feat,   // [B, T, 128]
    const int*    __restrict__ spans,  // [B, K, 2]
    const int*    __restrict__ lengths,// [B]
    float4*       __restrict__ out,    // [B, K, P, 128]
    int K, int T, int D4, int nwork, int nblk)
{
    const int tid = threadIdx.x;                 // d4 lane, 0..127

    int it = blockIdx.x;
    if (it >= nwork) return;

    // scalar data for the first item
    int bk = it >> 3;
    int b  = bk / K;
    int ca0 = __ldg(&spans[bk * 2 + 0]);
    int ca1 = __ldg(&spans[bk * 2 + 1]);
    int clen = __ldg(&lengths[b]);

    while (true) {
        const int pg = it & 7;

        // ---- span math for current item (uniform) ----
        const int Lm1 = clen - 1;
        int a0 = min(max(ca0, 0), Lm1);
        int a1 = min(max(ca1, 0), Lm1);
        const int s     = min(a0, a1);
        const int segm1 = max(a0, a1) - s;       // seglen - 1
        const float segf = (float)segm1;

        const int fbase = (b * T + s) * D4 + tid;
        const int obase = (bk * P_SAMPLES + pg * PG) * D4 + tid;

        // ---- issue feat loads (4-burst, MLP_p1 = 4) ----
        float4 f0[PG], f1[PG];
        float  w[PG];
        #pragma unroll
        for (int u = 0; u < PG; u++) {
            const int pp = pg * PG + u;
            const float t   = (float)pp / (float)(P_SAMPLES - 1);
            const float idx = t * segf;
            int i0 = (int)floorf(idx);
            i0 = min(i0, segm1);
            const int i1 = min(i0 + 1, segm1);
            w[u] = idx - (float)i0;
            f0[u] = feat[fbase + i0 * D4];
            f1[u] = feat[fbase + i1 * D4];
        }

        // ---- prefetch next item's scalars while feat loads are in flight ----
        const int it2 = it + nblk;
        const bool more = (it2 < nwork);
        if (more) {
            bk = it2 >> 3;
            b  = bk / K;
            ca0 = __ldg(&spans[bk * 2 + 0]);
            ca1 = __ldg(&spans[bk * 2 + 1]);
            clen = __ldg(&lengths[b]);
        }

        // ---- consume + store (grouped at item end, R6 schedule) ----
        #pragma unroll
        for (int u = 0; u < PG; u++) {
            float4 r;
            r.x = fmaf(w[u], f1[u].x - f0[u].x, f0[u].x);
            r.y = fmaf(w[u], f1[u].y - f0[u].y, f0[u].y);
            r.z = fmaf(w[u], f1[u].z - f0[u].z, f0[u].z);
            r.w = fmaf(w[u], f1[u].w - f0[u].w, f0[u].w);
            __stcs(&out[obase + u * D4], r);
        }

        if (!more) break;
        it = it2;
    }
}

extern "C" void kernel_launch(void* const* d_in, const int* in_sizes, int n_in,
                              void* d_out, int out_size)
{
    const float* feat    = (const float*)d_in[0];
    const int*   spans   = (const int*)d_in[1];
    const int*   lengths = (const int*)d_in[2];
    float*       out     = (float*)d_out;

    const int B  = in_sizes[2];                      // 16
    const int K  = in_sizes[1] / (2 * B);            // 64
    const int TD = in_sizes[0] / B;                  // T*D
    const int D  = out_size / (B * K * P_SAMPLES);   // 512
    const int T  = TD / D;                           // 4096
    const int D4 = D / 4;                            // 128

    const int nwork = B * K * (P_SAMPLES / PG);      // 8192
    const int nblk  = 148 * 16;                      // 2368: exact residency cap
    const int grid  = (nwork < nblk) ? nwork : nblk;
    roialign1d_kernel<<<grid, D4>>>(
        (const float4*)feat, spans, lengths, (float4*)out, K, T, D4, nwork, nblk);
}

// round 12
// speedup vs baseline: 1.0545x; 1.0545x over previous
#include <cuda_runtime.h>
#include <cuda_bf16.h>

// RoIAlign1D: feat [B,T,D] f32, spans [B,K,2] i32, lengths [B] i32 -> out [B,K,P,D] f32
// P = 16, D = 512.
//
// R12 = R6 blocking with 256-bit memory ops (sm_100+ ld/st.global.v8.f32).
// Block = (RoI, 2 samples), grid = B*K*8 = 8192, 128 threads. Thread tid ->
// sample u = tid>>6, 8-float chunk c = tid&63 (64 chunks cover the 512-float
// row). Per thread: 2x LDG.256 + 1x STG.256 (was 4x LDG.128 + 2x STG.128) --
// half the LSU/L1tex instruction traffic, same bytes in flight per warp.

#define P_SAMPLES 16
#define PG 2   // samples per block

#define LDG256(r, p)                                                          \
    asm volatile("ld.global.v8.f32 {%0,%1,%2,%3,%4,%5,%6,%7}, [%8];"          \
        : "=f"((r)[0]), "=f"((r)[1]), "=f"((r)[2]), "=f"((r)[3]),             \
          "=f"((r)[4]), "=f"((r)[5]), "=f"((r)[6]), "=f"((r)[7])              \
        : "l"(p))

#define STG256(p, r)                                                          \
    asm volatile("st.global.cs.v8.f32 [%0], {%1,%2,%3,%4,%5,%6,%7,%8};"       \
        :: "l"(p),                                                            \
           "f"((r)[0]), "f"((r)[1]), "f"((r)[2]), "f"((r)[3]),                \
           "f"((r)[4]), "f"((r)[5]), "f"((r)[6]), "f"((r)[7])                 \
        : "memory")

__global__ void __launch_bounds__(128, 16) roialign1d_kernel(
    const float* __restrict__ feat,    // [B, T, 512]
    const int*   __restrict__ spans,   // [B, K, 2]
    const int*   __restrict__ lengths, // [B]
    float*       __restrict__ out,     // [B, K, P, 512]
    int K, int T, int D)
{
    const int blk = blockIdx.x;                  // bk*8 + pg
    const int pg  = blk & 7;
    const int bk  = blk >> 3;                    // b*K + k
    const int b   = bk / K;
    const int u   = threadIdx.x >> 6;            // which of the 2 samples
    const int c   = threadIdx.x & 63;            // 8-float chunk within row

    // ---- span math, uniform across block ----
    const int Lm1 = __ldg(&lengths[b]) - 1;
    int a0 = __ldg(&spans[bk * 2 + 0]);
    int a1 = __ldg(&spans[bk * 2 + 1]);
    a0 = min(max(a0, 0), Lm1);
    a1 = min(max(a1, 0), Lm1);
    const int s     = min(a0, a1);
    const int segm1 = max(a0, a1) - s;           // seglen - 1
    const float segf = (float)segm1;

    // ---- per-sample index/weight (uniform within each 64-thread half) ----
    const int pp = pg * PG + u;
    const float t   = (float)pp / (float)(P_SAMPLES - 1);
    const float idx = t * segf;
    int i0 = (int)floorf(idx);
    i0 = min(i0, segm1);
    const int i1 = min(i0 + 1, segm1);
    const float w = idx - (float)i0;

    const int coff = c * 8;                      // float offset of chunk
    const float* p0 = feat + (size_t)(b * T + s + i0) * D + coff;
    const float* p1 = feat + (size_t)(b * T + s + i1) * D + coff;
    float* po = out + (size_t)(bk * P_SAMPLES + pp) * D + coff;

    float f0[8], f1[8], r[8];
    LDG256(f0, p0);
    LDG256(f1, p1);
    #pragma unroll
    for (int i = 0; i < 8; i++)
        r[i] = fmaf(w, f1[i] - f0[i], f0[i]);
    STG256(po, r);
}

extern "C" void kernel_launch(void* const* d_in, const int* in_sizes, int n_in,
                              void* d_out, int out_size)
{
    const float* feat    = (const float*)d_in[0];
    const int*   spans   = (const int*)d_in[1];
    const int*   lengths = (const int*)d_in[2];
    float*       out     = (float*)d_out;

    const int B  = in_sizes[2];                      // 16
    const int K  = in_sizes[1] / (2 * B);            // 64
    const int TD = in_sizes[0] / B;                  // T*D
    const int D  = out_size / (B * K * P_SAMPLES);   // 512
    const int T  = TD / D;                           // 4096

    const int nblocks = B * K * (P_SAMPLES / PG);    // 8192
    roialign1d_kernel<<<nblocks, 128>>>(
        feat, spans, lengths, out, K, T, D);
}

// round 13
// speedup vs baseline: 1.2156x; 1.1527x over previous
#include <cuda_runtime.h>
#include <cuda_bf16.h>

// RoIAlign1D: feat [B,T,D] f32, spans [B,K,2] i32, lengths [B] i32 -> out [B,K,P,D] f32
// P = 16, D = 512 (128 float4).
//
// R13 = R6 (best measured: 10.7us; grid B*K*8, 128 thr, PG=2, MLP_p1=4,
// 64-warp occ cap, __stcs stores, default L1-cached loads) + one safe cut:
// when w==0 the f1 operand is unused (multiplied by zero), so i1 is redirected
// to i0 -- the duplicate-address load merges in L1's pending-sector queue and
// the second L2 read disappears (~6% of read traffic: p=0, p=15, and any
// integral t*segm1). Output bit-identical.

#define P_SAMPLES 16
#define PG 2   // samples per block

__global__ void __launch_bounds__(128, 16) roialign1d_kernel(
    const float4* __restrict__ feat,   // [B, T, 128]
    const int*    __restrict__ spans,  // [B, K, 2]
    const int*    __restrict__ lengths,// [B]
    float4*       __restrict__ out,    // [B, K, P, 128]
    int K, int T, int D4)
{
    const int blk = blockIdx.x;                  // bk*8 + pg
    const int pg  = blk & 7;
    const int bk  = blk >> 3;                    // b*K + k
    const int b   = bk / K;
    const int tid = threadIdx.x;                 // d4 lane, 0..127

    // ---- span math, once per block (uniform) ----
    const int Lm1 = __ldg(&lengths[b]) - 1;
    int a0 = __ldg(&spans[bk * 2 + 0]);
    int a1 = __ldg(&spans[bk * 2 + 1]);
    a0 = min(max(a0, 0), Lm1);
    a1 = min(max(a1, 0), Lm1);
    const int s     = min(a0, a1);
    const int segm1 = max(a0, a1) - s;           // seglen - 1
    const float segf = (float)segm1;

    const int fbase = (b * T + s) * D4 + tid;
    const int obase = (bk * P_SAMPLES + pg * PG) * D4 + tid;

    float4 f0[PG], f1[PG];
    float  w[PG];
    #pragma unroll
    for (int u = 0; u < PG; u++) {
        const int pp = pg * PG + u;
        const float t   = (float)pp / (float)(P_SAMPLES - 1);
        const float idx = t * segf;
        int i0 = (int)floorf(idx);
        i0 = min(i0, segm1);
        int i1 = min(i0 + 1, segm1);
        w[u] = idx - (float)i0;
        if (w[u] == 0.0f) i1 = i0;               // f1 unused when w==0: dedupe load
        f0[u] = feat[fbase + i0 * D4];
        f1[u] = feat[fbase + i1 * D4];
    }
    #pragma unroll
    for (int u = 0; u < PG; u++) {
        float4 r;
        r.x = fmaf(w[u], f1[u].x - f0[u].x, f0[u].x);
        r.y = fmaf(w[u], f1[u].y - f0[u].y, f0[u].y);
        r.z = fmaf(w[u], f1[u].z - f0[u].z, f0[u].z);
        r.w = fmaf(w[u], f1[u].w - f0[u].w, f0[u].w);
        __stcs(&out[obase + u * D4], r);         // streaming store (best measured)
    }
}

extern "C" void kernel_launch(void* const* d_in, const int* in_sizes, int n_in,
                              void* d_out, int out_size)
{
    const float* feat    = (const float*)d_in[0];
    const int*   spans   = (const int*)d_in[1];
    const int*   lengths = (const int*)d_in[2];
    float*       out     = (float*)d_out;

    const int B  = in_sizes[2];                      // 16
    const int K  = in_sizes[1] / (2 * B);            // 64
    const int TD = in_sizes[0] / B;                  // T*D
    const int D  = out_size / (B * K * P_SAMPLES);   // 512
    const int T  = TD / D;                           // 4096
    const int D4 = D / 4;                            // 128

    const int nblocks = B * K * (P_SAMPLES / PG);    // 8192
    roialign1d_kernel<<<nblocks, D4>>>(
        (const float4*)feat, spans, lengths, (float4*)out, K, T, D4);
}